// round 15
// baseline (speedup 1.0000x reference)
#include <cuda_runtime.h>

// QNN via Heisenberg-picture Pauli propagation. One sample per thread.
// z_q = 30 sparse monomials in C_j=cos(x_j+w0_j), S_j=sin(x_j+w0_j).
// Coefficients built by 4 threads (one per z_q) OVERLAPPED with per-thread
// trig. The four z FMA chains are source-interleaved for explicit 4-way ILP.
// Softmax via shift-invariance (logit0 folded out at setup): e0 == 1,
// log2 domain, ex2.approx / rcp.approx. 256-thread blocks (measured best).
// Inputs: x [B,4], qw [3,4], W [6,4], b [6] (f32). Out: probs [B,6] f32.

#define LOG2E 1.4426950408889634f
#define TPB 256

__device__ __forceinline__ float ex2_approx(float v) {
    float r; asm("ex2.approx.ftz.f32 %0, %1;" : "=f"(r) : "f"(v)); return r;
}
__device__ __forceinline__ float rcp_approx(float v) {
    float r; asm("rcp.approx.ftz.f32 %0, %1;" : "=f"(r) : "f"(v)); return r;
}

#define CA0 0      // 6: z0
#define CA1 6      // 5: z1
#define CA2 11     // 6: z2
#define CA3 17     // 13: z3  (total 30)

__global__ __launch_bounds__(TPB) void qnn_kernel(
    const float4* __restrict__ x,
    const float*  __restrict__ qw,
    const float*  __restrict__ W,
    const float*  __restrict__ bias,
    float2*       __restrict__ out,
    int B)
{
    __shared__ float w0s[4];
    __shared__ float trig[16];
    __shared__ __align__(16) float cf[32];
    __shared__ __align__(16) float4 Wd[5];   // (W_k - W_0) * log2e, k=1..5
    __shared__ float bd[5];                  // (b_k - b_0) * log2e

    int t = threadIdx.x;
    int i = blockIdx.x * TPB + t;

    // hoist input load: DRAM/L2 latency overlaps setup
    float4 xv = (i < B) ? x[i] : make_float4(0.f, 0.f, 0.f, 0.f);

    if (t < 4) {
        w0s[t] = qw[t];
        float s, c;
        __sincosf(qw[4 + t], &s, &c); trig[t] = c;     trig[4 + t]  = s;
        __sincosf(qw[8 + t], &s, &c); trig[8 + t] = c; trig[12 + t] = s;
    }
    if (t >= 32 && t < 52) {     // 20 threads: Wd (k=1..5, col j=0..3)
        int k = (t - 32) >> 2, j = (t - 32) & 3;
        ((float*)Wd)[k * 4 + j] = (W[(k + 1) * 4 + j] - W[j]) * LOG2E;
    }
    if (t >= 52 && t < 57) {     // 5 threads: bd
        int k = t - 52;
        bd[k] = (bias[k + 1] - bias[0]) * LOG2E;
    }
    __syncthreads();

    // ---- per-thread trig + pair products, overlapped with coefficient build
    float C0, S0, C1, S1, C2, S2, C3, S3;
    __sincosf(xv.x + w0s[0], &S0, &C0);
    __sincosf(xv.y + w0s[1], &S1, &C1);
    __sincosf(xv.z + w0s[2], &S2, &C2);
    __sincosf(xv.w + w0s[3], &S3, &C3);

    float pc01 = C0 * C1, pc23 = C2 * C3, pc02 = C0 * C2, pc13 = C1 * C3;
    float ps01 = S0 * S1, ps23 = S2 * S3, ps02 = S0 * S2, ps13 = S1 * S3;
    float ps12 = S1 * S2, ps03 = S0 * S3, pcs23 = C2 * S3;
    float c0c2c3 = C0 * pc23;
    float c0s1s2 = C0 * ps12;

    // coefficient build spread over 4 threads (one per observable)
    if (t < 4) {
        float c0 = trig[0], c1 = trig[1], c2 = trig[2], c3 = trig[3];
        float s0 = trig[4], s1 = trig[5], s2 = trig[6], s3 = trig[7];
        if (t == 0) {
            float u0 = trig[8], v0 = trig[12];
            cf[CA0 + 0] =  u0 * c1 * c2 * c3;
            cf[CA0 + 1] = -u0 * c1 * c2 * s3;
            cf[CA0 + 2] = -u0 * s1 * c2 * c3;
            cf[CA0 + 3] = -u0 * s1 * s2 * s3;
            cf[CA0 + 4] = -v0 * s0 * s1;
            cf[CA0 + 5] = -v0 * c0 * c1;
        } else if (t == 1) {
            float u1 = trig[9], v1 = trig[13];
            cf[CA1 + 0] =  u1 * c0 * c1;
            cf[CA1 + 1] =  u1 * s0 * s1;
            cf[CA1 + 2] = -v1 * s1 * s2;
            cf[CA1 + 3] = -v1 * s1 * c2;
            cf[CA1 + 4] = -v1 * c1 * c2;
        } else if (t == 2) {
            float u2 = trig[10], v2 = trig[14];
            cf[CA2 + 0] =  u2 * c0 * c1 * c2;
            cf[CA2 + 1] = -u2 * c0 * s1 * c2;
            cf[CA2 + 2] = -u2 * s0 * c1 * c2;
            cf[CA2 + 3] = -u2 * s0 * s1 * s2;
            cf[CA2 + 4] = -v2 * s2 * s3;
            cf[CA2 + 5] = -v2 * c2 * c3;
        } else {
            float u3 = trig[11], v3 = trig[15];
            cf[CA3 + 0]  =  u3 * c0 * c1 * c2 * c3;
            cf[CA3 + 1]  = -u3 * c0 * c1 * s2 * c3;
            cf[CA3 + 2]  =  u3 * c0 * s1 * s2 * c3;
            cf[CA3 + 3]  = -u3 * c0 * s1 * s2 * s3;
            cf[CA3 + 4]  =  u3 * s0 * c1 * c2 * s3;
            cf[CA3 + 5]  = -u3 * s0 * c1 * s2 * s3;
            cf[CA3 + 6]  =  u3 * s0 * s1 * c2 * c3;
            cf[CA3 + 7]  =  u3 * s0 * s1 * s2 * s3;
            cf[CA3 + 8]  = -v3 * c0 * c1 * c3;
            cf[CA3 + 9]  = -v3 * c0 * s1 * c3;
            cf[CA3 + 10] = -v3 * c0 * s1 * s3;
            cf[CA3 + 11] = -v3 * s0 * c1 * s3;
            cf[CA3 + 12] = -v3 * s0 * s1 * s3;
        }
    }
    __syncthreads();

    if (i >= B) return;

    // four z-chains interleaved in source order: explicit 4-way ILP
    float z0 = cf[CA0 + 0] * (pc01 * C3);
    float z1 = cf[CA1 + 0] * c0c2c3;
    float z2 = cf[CA2 + 0] * pc13;
    float z3a = cf[CA3 + 0] * pc02;
    float z3b = cf[CA3 + 7] * S1;

    z0 = fmaf(cf[CA0 + 1], ps01 * pcs23, z0);
    z1 = fmaf(cf[CA1 + 1], ps02, z1);
    z2 = fmaf(cf[CA2 + 1], c0s1s2 * C3, z2);
    z3a = fmaf(cf[CA3 + 1], C1 * ps23, z3a);
    z3b = fmaf(cf[CA3 + 8], S1 * ps23, z3b);

    z0 = fmaf(cf[CA0 + 2], ps12 * C3, z0);
    z1 = fmaf(cf[CA1 + 2], C2, z1);
    z2 = fmaf(cf[CA2 + 2], ps01 * C2, z2);
    z3a = fmaf(cf[CA3 + 2], C0 * ps13, z3a);
    z3b = fmaf(cf[CA3 + 9], pc01 * S3, z3b);

    z0 = fmaf(cf[CA0 + 3], S0, z0);
    z1 = fmaf(cf[CA1 + 3], pc01 * ps23, z1);
    z2 = fmaf(cf[CA2 + 3], ps03, z2);
    z3a = fmaf(cf[CA3 + 3], S0 * (C1 * pc23), z3a);
    z3b = fmaf(cf[CA3 + 10], ps01 * pc23, z3b);

    z0 = fmaf(cf[CA0 + 4], c0c2c3, z0);
    z1 = fmaf(cf[CA1 + 4], ps13, z1);
    z2 = fmaf(cf[CA2 + 4], C3, z2);
    z3a = fmaf(cf[CA3 + 4], pcs23, z3a);
    z3b = fmaf(cf[CA3 + 11], c0s1s2, z3b);

    z0 = fmaf(cf[CA0 + 5], ps02, z0);
    z2 = fmaf(cf[CA2 + 5], ps01 * S2, z2);
    z3a = fmaf(cf[CA3 + 5], pc01 * S2, z3a);
    z3b = fmaf(cf[CA3 + 12], C1, z3b);

    z3a = fmaf(cf[CA3 + 6], ps02 * C3, z3a);
    float z3 = z3a + z3b;

    // softmax via shift-invariance: e0 = 1, e_k = exp2((W_k-W_0)z + (b_k-b_0))
    float eo[5];
    #pragma unroll
    for (int k = 0; k < 5; k++) {
        float4 w = Wd[k];
        float acc = bd[k];
        acc = fmaf(w.x, z0, acc);
        acc = fmaf(w.y, z1, acc);
        acc = fmaf(w.z, z2, acc);
        acc = fmaf(w.w, z3, acc);
        eo[k] = ex2_approx(acc);
    }
    float ssum = 1.0f + (((eo[0] + eo[1]) + (eo[2] + eo[3])) + eo[4]);
    float inv = rcp_approx(ssum);

    float2* o = out + (size_t)i * 3;
    o[0] = make_float2(inv, eo[0] * inv);
    o[1] = make_float2(eo[1] * inv, eo[2] * inv);
    o[2] = make_float2(eo[3] * inv, eo[4] * inv);
}

extern "C" void kernel_launch(void* const* d_in, const int* in_sizes, int n_in,
                              void* d_out, int out_size) {
    const float4* x  = (const float4*)d_in[0];
    const float*  qw = (const float*)d_in[1];
    const float*  W  = (const float*)d_in[2];
    const float*  b  = (const float*)d_in[3];
    float2* out = (float2*)d_out;
    int B = in_sizes[0] / 4;
    int blocks = (B + TPB - 1) / TPB;
    qnn_kernel<<<blocks, TPB>>>(x, qw, W, b, out, B);
}

// round 16
// speedup vs baseline: 2.8782x; 2.8782x over previous
#include <cuda_runtime.h>

// QNN via Heisenberg-picture Pauli propagation. One sample per thread.
// z_q = 30 sparse monomials in C_j=cos(x_j+w0_j), S_j=sin(x_j+w0_j).
// t0 builds uniform coefficients OVERLAPPED with per-thread trig.
// Softmax uses shift-invariance (logit0 subtracted at setup): e0 == 1,
// 5 logits via (W_k - W_0)z + (b_k - b_0), all in log2 domain, ex2.approx.
// [R13 configuration — best measured: 10.40 us harness]
// Inputs: x [B,4] f32, qw [3,4] f32, W [6,4] f32, b [6] f32. Out: [B,6] f32.

#define LOG2E 1.4426950408889634f

__device__ __forceinline__ float ex2_approx(float v) {
    float r; asm("ex2.approx.ftz.f32 %0, %1;" : "=f"(r) : "f"(v)); return r;
}
__device__ __forceinline__ float rcp_approx(float v) {
    float r; asm("rcp.approx.ftz.f32 %0, %1;" : "=f"(r) : "f"(v)); return r;
}

#define CA0 0      // 6: z0
#define CA1 6      // 5: z1
#define CA2 11     // 6: z2
#define CA3 17     // 13: z3  (total 30)

__global__ __launch_bounds__(256) void qnn_kernel(
    const float4* __restrict__ x,
    const float*  __restrict__ qw,
    const float*  __restrict__ W,
    const float*  __restrict__ bias,
    float2*       __restrict__ out,
    int B)
{
    __shared__ float w0s[4];
    __shared__ float trig[16];
    __shared__ __align__(16) float cf[32];
    __shared__ __align__(16) float4 Wd[5];   // (W_k - W_0) * log2e, k=1..5
    __shared__ float bd[5];                  // (b_k - b_0) * log2e

    int t = threadIdx.x;
    int i = blockIdx.x * 256 + t;

    // hoist input load: DRAM latency overlaps setup
    float4 xv = (i < B) ? x[i] : make_float4(0.f, 0.f, 0.f, 0.f);

    if (t < 4) {
        w0s[t] = qw[t];
        float s, c;
        __sincosf(qw[4 + t], &s, &c); trig[t] = c;     trig[4 + t]  = s;
        __sincosf(qw[8 + t], &s, &c); trig[8 + t] = c; trig[12 + t] = s;
    }
    if (t >= 32 && t < 52) {     // 20 threads: Wd rows (k=1..5, col j=0..3)
        int k = (t - 32) / 4 + 1, j = (t - 32) & 3;
        ((float*)Wd)[(k - 1) * 4 + j] = (W[k * 4 + j] - W[j]) * LOG2E;
    }
    if (t >= 52 && t < 57) {     // 5 threads: bd
        int k = t - 51;
        bd[k - 1] = (bias[k] - bias[0]) * LOG2E;
    }
    __syncthreads();

    // ---- per-thread trig + pair products, overlapped with t0's coefficients
    float C0, S0, C1, S1, C2, S2, C3, S3;
    __sincosf(xv.x + w0s[0], &S0, &C0);
    __sincosf(xv.y + w0s[1], &S1, &C1);
    __sincosf(xv.z + w0s[2], &S2, &C2);
    __sincosf(xv.w + w0s[3], &S3, &C3);

    float pc01 = C0 * C1, pc23 = C2 * C3, pc02 = C0 * C2, pc13 = C1 * C3;
    float ps01 = S0 * S1, ps23 = S2 * S3, ps02 = S0 * S2, ps13 = S1 * S3;
    float ps12 = S1 * S2, ps03 = S0 * S3, pcs23 = C2 * S3;
    float c0c2c3 = C0 * pc23;
    float c0s1s2 = C0 * ps12;

    if (t == 0) {
        float c0 = trig[0], c1 = trig[1], c2 = trig[2], c3 = trig[3];
        float s0 = trig[4], s1 = trig[5], s2 = trig[6], s3 = trig[7];
        float u0 = trig[8], u1 = trig[9], u2 = trig[10], u3 = trig[11];
        float v0 = trig[12], v1 = trig[13], v2 = trig[14], v3 = trig[15];

        cf[CA0 + 0] =  u0 * c1 * c2 * c3;
        cf[CA0 + 1] = -u0 * c1 * c2 * s3;
        cf[CA0 + 2] = -u0 * s1 * c2 * c3;
        cf[CA0 + 3] = -u0 * s1 * s2 * s3;
        cf[CA0 + 4] = -v0 * s0 * s1;
        cf[CA0 + 5] = -v0 * c0 * c1;

        cf[CA1 + 0] =  u1 * c0 * c1;
        cf[CA1 + 1] =  u1 * s0 * s1;
        cf[CA1 + 2] = -v1 * s1 * s2;
        cf[CA1 + 3] = -v1 * s1 * c2;
        cf[CA1 + 4] = -v1 * c1 * c2;

        cf[CA2 + 0] =  u2 * c0 * c1 * c2;
        cf[CA2 + 1] = -u2 * c0 * s1 * c2;
        cf[CA2 + 2] = -u2 * s0 * c1 * c2;
        cf[CA2 + 3] = -u2 * s0 * s1 * s2;
        cf[CA2 + 4] = -v2 * s2 * s3;
        cf[CA2 + 5] = -v2 * c2 * c3;

        cf[CA3 + 0]  =  u3 * c0 * c1 * c2 * c3;
        cf[CA3 + 1]  = -u3 * c0 * c1 * s2 * c3;
        cf[CA3 + 2]  =  u3 * c0 * s1 * s2 * c3;
        cf[CA3 + 3]  = -u3 * c0 * s1 * s2 * s3;
        cf[CA3 + 4]  =  u3 * s0 * c1 * c2 * s3;
        cf[CA3 + 5]  = -u3 * s0 * c1 * s2 * s3;
        cf[CA3 + 6]  =  u3 * s0 * s1 * c2 * c3;
        cf[CA3 + 7]  =  u3 * s0 * s1 * s2 * s3;
        cf[CA3 + 8]  = -v3 * c0 * c1 * c3;
        cf[CA3 + 9]  = -v3 * c0 * s1 * c3;
        cf[CA3 + 10] = -v3 * c0 * s1 * s3;
        cf[CA3 + 11] = -v3 * s0 * c1 * s3;
        cf[CA3 + 12] = -v3 * s0 * s1 * s3;
        cf[30] = 0.f; cf[31] = 0.f;
    }
    __syncthreads();

    if (i >= B) return;

    float z0 = cf[CA0 + 0] * (pc01 * C3);
    z0 = fmaf(cf[CA0 + 1], ps01 * pcs23, z0);
    z0 = fmaf(cf[CA0 + 2], ps12 * C3, z0);
    z0 = fmaf(cf[CA0 + 3], S0, z0);
    z0 = fmaf(cf[CA0 + 4], c0c2c3, z0);
    z0 = fmaf(cf[CA0 + 5], ps02, z0);

    float z1 = cf[CA1 + 0] * c0c2c3;
    z1 = fmaf(cf[CA1 + 1], ps02, z1);
    z1 = fmaf(cf[CA1 + 2], C2, z1);
    z1 = fmaf(cf[CA1 + 3], pc01 * ps23, z1);
    z1 = fmaf(cf[CA1 + 4], ps13, z1);

    float z2 = cf[CA2 + 0] * pc13;
    z2 = fmaf(cf[CA2 + 1], c0s1s2 * C3, z2);
    z2 = fmaf(cf[CA2 + 2], ps01 * C2, z2);
    z2 = fmaf(cf[CA2 + 3], ps03, z2);
    z2 = fmaf(cf[CA2 + 4], C3, z2);
    z2 = fmaf(cf[CA2 + 5], ps01 * S2, z2);

    float z3a = cf[CA3 + 0] * pc02;
    z3a = fmaf(cf[CA3 + 1],  C1 * ps23, z3a);
    z3a = fmaf(cf[CA3 + 2],  C0 * ps13, z3a);
    z3a = fmaf(cf[CA3 + 3],  S0 * (C1 * pc23), z3a);
    z3a = fmaf(cf[CA3 + 4],  pcs23, z3a);
    z3a = fmaf(cf[CA3 + 5],  pc01 * S2, z3a);
    z3a = fmaf(cf[CA3 + 6],  ps02 * C3, z3a);
    float z3b = cf[CA3 + 7] * S1;
    z3b = fmaf(cf[CA3 + 8],  S1 * ps23, z3b);
    z3b = fmaf(cf[CA3 + 9],  pc01 * S3, z3b);
    z3b = fmaf(cf[CA3 + 10], ps01 * pc23, z3b);
    z3b = fmaf(cf[CA3 + 11], c0s1s2, z3b);
    z3b = fmaf(cf[CA3 + 12], C1, z3b);
    float z3 = z3a + z3b;

    // softmax via shift-invariance: e0 = 1, e_k = exp2((W_k-W_0)z + (b_k-b_0))
    float eo[5];
    #pragma unroll
    for (int k = 0; k < 5; k++) {
        float4 w = Wd[k];
        float acc = bd[k];
        acc = fmaf(w.x, z0, acc);
        acc = fmaf(w.y, z1, acc);
        acc = fmaf(w.z, z2, acc);
        acc = fmaf(w.w, z3, acc);
        eo[k] = ex2_approx(acc);
    }
    float ssum = 1.0f + (((eo[0] + eo[1]) + (eo[2] + eo[3])) + eo[4]);
    float inv = rcp_approx(ssum);

    out[i * 3 + 0] = make_float2(inv, eo[0] * inv);
    out[i * 3 + 1] = make_float2(eo[1] * inv, eo[2] * inv);
    out[i * 3 + 2] = make_float2(eo[3] * inv, eo[4] * inv);
}

extern "C" void kernel_launch(void* const* d_in, const int* in_sizes, int n_in,
                              void* d_out, int out_size) {
    const float4* x  = (const float4*)d_in[0];
    const float*  qw = (const float*)d_in[1];
    const float*  W  = (const float*)d_in[2];
    const float*  b  = (const float*)d_in[3];
    float2* out = (float2*)d_out;
    int B = in_sizes[0] / 4;
    int threads = 256;
    int blocks = (B + threads - 1) / threads;
    qnn_kernel<<<blocks, threads>>>(x, qw, W, b, out, B);
}